// round 15
// baseline (speedup 1.0000x reference)
#include <cuda_runtime.h>
#include <cuda_fp16.h>
#include <cstdint>

#define E_TOT   300000
#define N_NODES 50000
#define NPAD    (N_NODES + 128)
#define TILE_M  128
#define NTH     512

__device__ __half g_P[(size_t)NPAD * 512];     // [node][ Ps(256) | Pr(256) ] fp16
__device__ __half g_W1sT[256 * 128];           // [n][k]
__device__ __half g_W1rT[256 * 128];
__device__ __half g_W1eT[256 * 128];
__device__ __half g_W2T[128 * 256];

// ---- main-kernel smem byte offsets ----
#define OF_B1   0        // 256 f
#define OF_B2   1024     // 128 f
#define OF_G    1536     // 128 f
#define OF_BT   2048     // 128 f
#define OF_SI   2560     // 128 i
#define OF_RI   3072     // 128 i
#define OF_X0   3584     // 128*72 half = 18432
#define OF_X1   22016    // ends 40448
#define OF_W1E  40448    // 256*136 half = 69632, ends 110080
#define OF_W2R  110080   // 128*264 half = 67584, ends 177664
#define OF_H    3584     // H overlays X0/X1/W1E (dead after GEMM1e); 128*264*2 = 67584 <= 106496
#define SMEM_BYTES 177664

// ---- precompute-kernel smem ----
#define PF_X0  0         // 128*72 half
#define PF_X1  18432
#define PF_W0  36864     // 256*72 half
#define PF_W1B 73728
#define SMEM_PRE 110592

#define XS  72    // X chunk row stride (half), K=64 chunks
#define WS  72    // precompute W panel row stride (half)
#define W1S 136   // resident W1e row stride (half)
#define W2S 264   // resident W2 row stride (half)
#define HS  264
#define OS  132

__device__ __forceinline__ uint32_t smem_u32(const void* p) {
    uint32_t a;
    asm("{ .reg .u64 t; cvta.to.shared.u64 t, %1; cvt.u32.u64 %0, t; }" : "=r"(a) : "l"(p));
    return a;
}
__device__ __forceinline__ uint32_t pkh2(float lo, float hi) {
    uint32_t r; asm("cvt.rn.f16x2.f32 %0, %1, %2;" : "=r"(r) : "f"(hi), "f"(lo)); return r;
}
__device__ __forceinline__ void mma16(float (&d)[4], const uint32_t (&a)[4],
                                      uint32_t b0, uint32_t b1) {
    asm volatile("mma.sync.aligned.m16n8k16.row.col.f32.f16.f16.f32 "
        "{%0,%1,%2,%3}, {%4,%5,%6,%7}, {%8,%9}, {%0,%1,%2,%3};"
        : "+f"(d[0]), "+f"(d[1]), "+f"(d[2]), "+f"(d[3])
        : "r"(a[0]), "r"(a[1]), "r"(a[2]), "r"(a[3]), "r"(b0), "r"(b1));
}
__device__ __forceinline__ void ldsm4(uint32_t (&r)[4], uint32_t addr) {
    asm volatile("ldmatrix.sync.aligned.m8n8.x4.shared.b16 {%0,%1,%2,%3}, [%4];"
        : "=r"(r[0]), "=r"(r[1]), "=r"(r[2]), "=r"(r[3]) : "r"(addr));
}
#define CP16(dst, src) asm volatile("cp.async.ca.shared.global [%0], [%1], 16;" :: "r"(dst), "l"(src) : "memory")
#define CP_COMMIT()    asm volatile("cp.async.commit_group;" ::: "memory")
#define CP_WAIT0()     asm volatile("cp.async.wait_group 0;" ::: "memory")
#define CP_WAIT1()     asm volatile("cp.async.wait_group 1;" ::: "memory")
#define STSV4(a, v)    asm volatile("st.shared.v4.b32 [%0], {%1,%2,%3,%4};" :: "r"(a), "r"((v).x), "r"((v).y), "r"((v).z), "r"((v).w) : "memory")

// convert 16 fp32 (4 float4) -> 2 uint4 of f16x2 and store at smem addr, addr+16
__device__ __forceinline__ void cvt_store32B(uint32_t addr, const float4 fv[4]) {
    uint4 o0, o1;
    o0.x = pkh2(fv[0].x, fv[0].y); o0.y = pkh2(fv[0].z, fv[0].w);
    o0.z = pkh2(fv[1].x, fv[1].y); o0.w = pkh2(fv[1].z, fv[1].w);
    o1.x = pkh2(fv[2].x, fv[2].y); o1.y = pkh2(fv[2].z, fv[2].w);
    o1.z = pkh2(fv[3].x, fv[3].y); o1.w = pkh2(fv[3].z, fv[3].w);
    STSV4(addr, o0);
    STSV4(addr + 16, o1);
}

// ---------------- cvt: weights only (W1 split+transpose, W2 transpose) ----------------
__global__ void cvt_w_kernel(const float* __restrict__ W1,
                             const float* __restrict__ W2) {
    const int WTOT = 4 * 32768;
    for (int j = blockIdx.x * blockDim.x + threadIdx.x; j < WTOT;
         j += gridDim.x * blockDim.x) {
        if (j < 3 * 32768) {
            int sec = j >> 15, m = j & 32767;
            int n = m >> 7, k = m & 127;
            float v = W1[(sec * 128 + k) * 256 + n];
            __half* dst = (sec == 0) ? g_W1sT : (sec == 1) ? g_W1rT : g_W1eT;
            dst[m] = __float2half_rn(v);
        } else {
            int m = j - 3 * 32768;
            int n = m >> 8, k = m & 255;
            g_W2T[m] = __float2half_rn(W2[k * 128 + n]);
        }
    }
}

// ---------------- precompute: P[n] = node[n] @ [W1s | W1r] (fp32 node read) ----------------
__global__ __launch_bounds__(512, 1)
void precompute_kernel(const float* __restrict__ node)
{
    extern __shared__ char smem[];
    const int tid = threadIdx.x;
    const int wid = tid >> 5, lane = tid & 31;
    const int lr = lane >> 2, lc = lane & 3;
    const int wm = wid >> 2, wn = wid & 3;
    const int n0 = blockIdx.x * 128;
    const __half* WT = blockIdx.y ? g_W1rT : g_W1sT;

    const int r = tid >> 2, q = tid & 3;
    int nr = n0 + r; if (nr >= N_NODES) nr = N_NODES - 1;
    const float* pA = node + (size_t)nr * 128 + q * 16;
    const int nw = tid >> 1, hw = tid & 1;
    const __half* pW = WT + (size_t)nw * 128 + hw * 32;

    const uint32_t sbX[2] = { smem_u32(smem + PF_X0), smem_u32(smem + PF_X1) };
    const uint32_t sbW[2] = { smem_u32(smem + PF_W0), smem_u32(smem + PF_W1B) };
    const uint32_t dX = (uint32_t)(r * XS + q * 16) * 2;
    const uint32_t dW = (uint32_t)(nw * WS + hw * 32) * 2;

    const int aoff_row = lane & 15;
    const int aoff_k   = (lane >> 4) << 3;
    const int boff_n   = ((lane >> 4) << 3) + (lane & 7);
    const int boff_k   = ((lane >> 3) & 1) << 3;

    {
        #pragma unroll
        for (int s = 0; s < 4; s++) CP16(sbW[0] + dW + 16 * s, pW + 8 * s);
        CP_COMMIT();
        float4 fv[4];
        #pragma unroll
        for (int s = 0; s < 4; s++) fv[s] = *(const float4*)(pA + 4 * s);
        cvt_store32B(sbX[0] + dX, fv);
        CP_WAIT0();
    }
    __syncthreads();

    float acc[2][8][4];
    #pragma unroll
    for (int i = 0; i < 2; i++)
        #pragma unroll
        for (int j = 0; j < 8; j++)
            #pragma unroll
            for (int qq = 0; qq < 4; qq++) acc[i][j][qq] = 0.f;

    for (int c = 0; c < 2; c++) {
        const bool pre = (c == 0);
        float4 fv[4];
        if (pre) {
            #pragma unroll
            for (int s = 0; s < 4; s++) CP16(sbW[1] + dW + 16 * s, pW + 64 + 8 * s);
            CP_COMMIT();
            #pragma unroll
            for (int s = 0; s < 4; s++) fv[s] = *(const float4*)(pA + 64 + 4 * s);
        }
        const uint32_t xb = sbX[c], wb = sbW[c];
        #pragma unroll
        for (int ks = 0; ks < 4; ks++) {
            uint32_t A[2][4];
            #pragma unroll
            for (int i = 0; i < 2; i++)
                ldsm4(A[i], xb + (uint32_t)((wm * 32 + i * 16 + aoff_row) * XS + ks * 16 + aoff_k) * 2);
            #pragma unroll
            for (int jp = 0; jp < 4; jp++) {
                uint32_t B[4];
                ldsm4(B, wb + (uint32_t)((wn * 64 + jp * 16 + boff_n) * WS + ks * 16 + boff_k) * 2);
                mma16(acc[0][2 * jp],     A[0], B[0], B[1]);
                mma16(acc[1][2 * jp],     A[1], B[0], B[1]);
                mma16(acc[0][2 * jp + 1], A[0], B[2], B[3]);
                mma16(acc[1][2 * jp + 1], A[1], B[2], B[3]);
            }
        }
        if (pre) {
            cvt_store32B(sbX[1] + dX, fv);
            CP_WAIT0();
        }
        __syncthreads();
    }

    const int cbase = blockIdx.y * 256;
    #pragma unroll
    for (int i = 0; i < 2; i++) {
        int row = n0 + wm * 32 + i * 16 + lr;
        #pragma unroll
        for (int j = 0; j < 8; j++) {
            int col = wn * 64 + j * 8 + 2 * lc;
            if (row < N_NODES)
                *(uint32_t*)(g_P + (size_t)row * 512 + cbase + col) = pkh2(acc[i][j][0], acc[i][j][1]);
            if (row + 8 < N_NODES)
                *(uint32_t*)(g_P + (size_t)(row + 8) * 512 + cbase + col) = pkh2(acc[i][j][2], acc[i][j][3]);
        }
    }
}

// ---------------- main kernel: resident W (overlapped load), wait-free GEMM2 ----------------
__global__ __launch_bounds__(NTH, 1)
void edge_mlp_h(const float* __restrict__ edge_attr,
                const int*   __restrict__ eidx,
                const float* __restrict__ b1,
                const float* __restrict__ b2,
                const float* __restrict__ gamma,
                const float* __restrict__ beta,
                float* __restrict__ out)
{
    extern __shared__ char smem[];
    float* smf = (float*)smem;
    const int tid = threadIdx.x;
    const int wid = tid >> 5, lane = tid & 31;
    const int lr = lane >> 2, lc = lane & 3;
    const int wm = wid >> 2, wn = wid & 3;
    const int e0 = blockIdx.x * TILE_M;

    if (tid < 256) smf[OF_B1 / 4 + tid] = b1[tid];
    if (tid < 128) {
        smf[OF_B2 / 4 + tid] = b2[tid];
        smf[OF_G  / 4 + tid] = gamma[tid];
        smf[OF_BT / 4 + tid] = beta[tid];
        int e = e0 + tid;
        bool ok = e < E_TOT;
        ((int*)(smem + OF_SI))[tid] = ok ? eidx[e] : 0;
        ((int*)(smem + OF_RI))[tid] = ok ? eidx[E_TOT + e] : 0;
    }

    const int r = tid >> 2, q = tid & 3;
    int eMine = e0 + r; if (eMine >= E_TOT) eMine = e0;
    const float* pE = edge_attr + (size_t)eMine * 128 + q * 16;    // + c*64

    const uint32_t sbX[2] = { smem_u32(smem + OF_X0), smem_u32(smem + OF_X1) };
    const uint32_t sbW1 = smem_u32(smem + OF_W1E);
    const uint32_t sbW2 = smem_u32(smem + OF_W2R);
    const uint32_t sbH  = smem_u32(smem + OF_H);
    const uint32_t dX = (uint32_t)(r * XS + q * 16) * 2;

    const int aoff_row = lane & 15;
    const int aoff_k   = (lane >> 4) << 3;
    const int boff_n   = ((lane >> 4) << 3) + (lane & 7);
    const int boff_k   = ((lane >> 3) & 1) << 3;

    // ---- prologue ----
    // group0: W1e full (69.6 KB); group1: W2 full (67.6 KB); X chunk0 via LDG+cvt+STS.
    {
        int n = tid >> 1, h = tid & 1;
        const __half* s1 = g_W1eT + (size_t)n * 128 + h * 64;
        uint32_t d1 = sbW1 + (uint32_t)(n * W1S + h * 64) * 2;
        #pragma unroll
        for (int s = 0; s < 8; s++) CP16(d1 + 16 * s, s1 + 8 * s);
        CP_COMMIT();                              // group 0 = W1e
        const __half* s2 = g_W2T + (size_t)r * 256 + q * 64;
        uint32_t d2 = sbW2 + (uint32_t)(r * W2S + q * 64) * 2;
        #pragma unroll
        for (int s = 0; s < 8; s++) CP16(d2 + 16 * s, s2 + 8 * s);
        CP_COMMIT();                              // group 1 = W2
        float4 fv[4];
        #pragma unroll
        for (int s = 0; s < 4; s++) fv[s] = *(const float4*)(pE + 4 * s);
        cvt_store32B(sbX[0] + dX, fv);
        CP_WAIT1();                               // W1e done; W2 may still be in flight
    }
    __syncthreads();

    // ======== GEMM1e: accE[128x256] = E[128x128] @ W1e (resident), 2 chunks K=64 ========
    float acc[2][8][4];
    #pragma unroll
    for (int i = 0; i < 2; i++)
        #pragma unroll
        for (int j = 0; j < 8; j++)
            #pragma unroll
            for (int qq = 0; qq < 4; qq++) acc[i][j][qq] = 0.f;

    for (int c = 0; c < 2; c++) {
        const bool pre = (c == 0);
        float4 fv[4];
        if (pre) {
            #pragma unroll
            for (int s = 0; s < 4; s++) fv[s] = *(const float4*)(pE + 64 + 4 * s);
        }
        const uint32_t xb = sbX[c];
        #pragma unroll
        for (int ks = 0; ks < 4; ks++) {
            uint32_t A[2][4];
            #pragma unroll
            for (int i = 0; i < 2; i++)
                ldsm4(A[i], xb + (uint32_t)((wm * 32 + i * 16 + aoff_row) * XS + ks * 16 + aoff_k) * 2);
            #pragma unroll
            for (int jp = 0; jp < 4; jp++) {
                uint32_t B[4];
                ldsm4(B, sbW1 + (uint32_t)((wn * 64 + jp * 16 + boff_n) * W1S + c * 64 + ks * 16 + boff_k) * 2);
                mma16(acc[0][2 * jp],     A[0], B[0], B[1]);
                mma16(acc[1][2 * jp],     A[1], B[0], B[1]);
                mma16(acc[0][2 * jp + 1], A[0], B[2], B[3]);
                mma16(acc[1][2 * jp + 1], A[1], B[2], B[3]);
            }
        }
        if (pre) cvt_store32B(sbX[1] + dX, fv);
        __syncthreads();
    }

    // ======== epilogue 1: H = fp16(relu(accE + Ps + Pr + b1)) -> H region (overlays X/W1e) ========
    {
        __half* Hh = (__half*)(smem + OF_H);
        const int* sI = (const int*)(smem + OF_SI);
        const int* rI = (const int*)(smem + OF_RI);
        #pragma unroll
        for (int i = 0; i < 2; i++) {
            int r0 = wm * 32 + i * 16 + lr;
            const __half* P0s = g_P + (size_t)sI[r0] * 512;
            const __half* P0r = g_P + (size_t)rI[r0] * 512 + 256;
            const __half* P1s = g_P + (size_t)sI[r0 + 8] * 512;
            const __half* P1r = g_P + (size_t)rI[r0 + 8] * 512 + 256;
            #pragma unroll
            for (int j = 0; j < 8; j++) {
                int col = wn * 64 + j * 8 + 2 * lc;
                float2 ps0 = __half22float2(*(const __half2*)(P0s + col));
                float2 pr0 = __half22float2(*(const __half2*)(P0r + col));
                float2 ps1 = __half22float2(*(const __half2*)(P1s + col));
                float2 pr1 = __half22float2(*(const __half2*)(P1r + col));
                float g0 = smf[OF_B1 / 4 + col], g1 = smf[OF_B1 / 4 + col + 1];
                *(uint32_t*)(Hh + r0 * HS + col) =
                    pkh2(fmaxf(acc[i][j][0] + ps0.x + pr0.x + g0, 0.f),
                         fmaxf(acc[i][j][1] + ps0.y + pr0.y + g1, 0.f));
                *(uint32_t*)(Hh + (r0 + 8) * HS + col) =
                    pkh2(fmaxf(acc[i][j][2] + ps1.x + pr1.x + g0, 0.f),
                         fmaxf(acc[i][j][3] + ps1.y + pr1.y + g1, 0.f));
            }
        }
        CP_WAIT0();   // W2 fully arrived (long since overlapped)
    }
    __syncthreads();

    // ======== GEMM2: C2[128x128] = H[128x256] @ W2 (resident, zero waits/syncs) ========
    float acc2[2][4][4];
    #pragma unroll
    for (int i = 0; i < 2; i++)
        #pragma unroll
        for (int j = 0; j < 4; j++)
            #pragma unroll
            for (int qq = 0; qq < 4; qq++) acc2[i][j][qq] = 0.f;

    for (int c = 0; c < 4; c++) {
        #pragma unroll
        for (int ks = 0; ks < 4; ks++) {
            uint32_t A[2][4];
            #pragma unroll
            for (int i = 0; i < 2; i++)
                ldsm4(A[i], sbH + (uint32_t)((wm * 32 + i * 16 + aoff_row) * HS + c * 64 + ks * 16 + aoff_k) * 2);
            #pragma unroll
            for (int jp = 0; jp < 2; jp++) {
                uint32_t B[4];
                ldsm4(B, sbW2 + (uint32_t)((wn * 32 + jp * 16 + boff_n) * W2S + c * 64 + ks * 16 + boff_k) * 2);
                mma16(acc2[0][2 * jp],     A[0], B[0], B[1]);
                mma16(acc2[1][2 * jp],     A[1], B[0], B[1]);
                mma16(acc2[0][2 * jp + 1], A[0], B[2], B[3]);
                mma16(acc2[1][2 * jp + 1], A[1], B[2], B[3]);
            }
        }
    }
    __syncthreads();   // all H reads complete before Of overwrites region

    // ======== epilogue 2: Of = C2 + b2 ; LayerNorm -> out ========
    {
        float* Of = (float*)(smem + OF_H);
        #pragma unroll
        for (int i = 0; i < 2; i++) {
            int r0 = wm * 32 + i * 16 + lr;
            #pragma unroll
            for (int j = 0; j < 4; j++) {
                int col = wn * 32 + j * 8 + 2 * lc;
                float g0 = smf[OF_B2 / 4 + col], g1 = smf[OF_B2 / 4 + col + 1];
                Of[r0 * OS + col]           = acc2[i][j][0] + g0;
                Of[r0 * OS + col + 1]       = acc2[i][j][1] + g1;
                Of[(r0 + 8) * OS + col]     = acc2[i][j][2] + g0;
                Of[(r0 + 8) * OS + col + 1] = acc2[i][j][3] + g1;
            }
        }
    }
    __syncthreads();
    {
        const float* Of = (const float*)(smem + OF_H);
        float4 ga = *(const float4*)(smf + OF_G  / 4 + 4 * lane);
        float4 bt = *(const float4*)(smf + OF_BT / 4 + 4 * lane);
        #pragma unroll
        for (int rr = 0; rr < 8; rr++) {
            int row = wid * 8 + rr;
            int e = e0 + row;
            float4 v = *(const float4*)(Of + row * OS + 4 * lane);
            float s = v.x + v.y + v.z + v.w;
            float qs = v.x * v.x + v.y * v.y + v.z * v.z + v.w * v.w;
            #pragma unroll
            for (int o = 16; o > 0; o >>= 1) {
                s  += __shfl_xor_sync(0xffffffffu, s, o);
                qs += __shfl_xor_sync(0xffffffffu, qs, o);
            }
            float mean = s * (1.0f / 128.0f);
            float var  = qs * (1.0f / 128.0f) - mean * mean;
            float inv  = rsqrtf(var + 1e-5f);
            if (e < E_TOT) {
                float4 o4;
                o4.x = (v.x - mean) * inv * ga.x + bt.x;
                o4.y = (v.y - mean) * inv * ga.y + bt.y;
                o4.z = (v.z - mean) * inv * ga.z + bt.z;
                o4.w = (v.w - mean) * inv * ga.w + bt.w;
                *(float4*)(out + (size_t)e * 128 + 4 * lane) = o4;
            }
        }
    }
}

extern "C" void kernel_launch(void* const* d_in, const int* in_sizes, int n_in,
                              void* d_out, int out_size)
{
    (void)in_sizes; (void)n_in; (void)out_size;
    cvt_w_kernel<<<512, 256>>>((const float*)d_in[3], (const float*)d_in[5]);
    cudaFuncSetAttribute(precompute_kernel,
                         cudaFuncAttributeMaxDynamicSharedMemorySize, SMEM_PRE);
    precompute_kernel<<<dim3((N_NODES + 127) / 128, 2), 512, SMEM_PRE>>>(
        (const float*)d_in[0]);
    cudaFuncSetAttribute(edge_mlp_h,
                         cudaFuncAttributeMaxDynamicSharedMemorySize, SMEM_BYTES);
    dim3 grid((E_TOT + TILE_M - 1) / TILE_M);
    edge_mlp_h<<<grid, NTH, SMEM_BYTES>>>(
        (const float*)d_in[1],   // edge_contact_attr
        (const int*)  d_in[2],   // edge_contact_index
        (const float*)d_in[4],   // b1
        (const float*)d_in[6],   // b2
        (const float*)d_in[7],   // ln_gamma
        (const float*)d_in[8],   // ln_beta
        (float*)d_out);
}

// round 16
// speedup vs baseline: 1.1602x; 1.1602x over previous
#include <cuda_runtime.h>
#include <cuda_fp16.h>
#include <cstdint>

#define E_TOT   300000
#define N_NODES 50000
#define NPAD    (N_NODES + 128)
#define TILE_M  128
#define NTILES  ((E_TOT + TILE_M - 1) / TILE_M)   // 2344
#define NTH     512
#define GRIDX   148

__device__ __half g_P[(size_t)NPAD * 512];     // [node][ Ps(256) | Pr(256) ] fp16
__device__ __half g_W1sT[256 * 128];           // [n][k]
__device__ __half g_W1rT[256 * 128];
__device__ __half g_W1eT[256 * 128];
__device__ __half g_W2T[128 * 256];

// ---- main-kernel smem byte offsets ----
#define OF_B1   0        // 256 f
#define OF_B2   1024     // 128 f
#define OF_G    1536     // 128 f
#define OF_BT   2048     // 128 f
#define OF_SI   2560     // 128 i
#define OF_RI   3072     // 128 i
#define OF_X0   3584     // 128*72 half = 18432
#define OF_X1   22016    // ends 40448
#define OF_W10  40448    // W1e panel buf0: 256*72 half = 36864
#define OF_W11  77312    // W1e panel buf1, ends 114176
#define OF_HW   40448    // H (128*264 half = 67584) / Of (128*132 f = 67584) overlay W1 bufs, end 108032
#define OF_W2R  114176   // resident W2: 128*264 half = 67584, ends 181760
#define SMEM_BYTES 181760

// ---- precompute-kernel smem (merged: X full K=128, W panels streamed) ----
#define PF_X   0         // 128*136 half = 34816
#define PF_W0  34816     // 256*72 half = 36864
#define PF_W1B 71680     // ends 108544
#define SMEM_PRE 108544

#define XS  72    // main X chunk row stride (half), K=64
#define PXS 136   // precompute X row stride (half), K=128
#define WS  72    // streamed W panel row stride (half)
#define W2S 264   // resident W2 row stride (half)
#define HS  264
#define OS  132

__device__ __forceinline__ uint32_t smem_u32(const void* p) {
    uint32_t a;
    asm("{ .reg .u64 t; cvta.to.shared.u64 t, %1; cvt.u32.u64 %0, t; }" : "=r"(a) : "l"(p));
    return a;
}
__device__ __forceinline__ uint32_t pkh2(float lo, float hi) {
    uint32_t r; asm("cvt.rn.f16x2.f32 %0, %1, %2;" : "=r"(r) : "f"(hi), "f"(lo)); return r;
}
__device__ __forceinline__ void mma16(float (&d)[4], const uint32_t (&a)[4],
                                      uint32_t b0, uint32_t b1) {
    asm volatile("mma.sync.aligned.m16n8k16.row.col.f32.f16.f16.f32 "
        "{%0,%1,%2,%3}, {%4,%5,%6,%7}, {%8,%9}, {%0,%1,%2,%3};"
        : "+f"(d[0]), "+f"(d[1]), "+f"(d[2]), "+f"(d[3])
        : "r"(a[0]), "r"(a[1]), "r"(a[2]), "r"(a[3]), "r"(b0), "r"(b1));
}
__device__ __forceinline__ void ldsm4(uint32_t (&r)[4], uint32_t addr) {
    asm volatile("ldmatrix.sync.aligned.m8n8.x4.shared.b16 {%0,%1,%2,%3}, [%4];"
        : "=r"(r[0]), "=r"(r[1]), "=r"(r[2]), "=r"(r[3]) : "r"(addr));
}
#define CP16(dst, src) asm volatile("cp.async.ca.shared.global [%0], [%1], 16;" :: "r"(dst), "l"(src) : "memory")
#define CP_COMMIT()    asm volatile("cp.async.commit_group;" ::: "memory")
#define CP_WAIT0()     asm volatile("cp.async.wait_group 0;" ::: "memory")
#define STSV4(a, v)    asm volatile("st.shared.v4.b32 [%0], {%1,%2,%3,%4};" :: "r"(a), "r"((v).x), "r"((v).y), "r"((v).z), "r"((v).w) : "memory")

__device__ __forceinline__ void cvt_store32B(uint32_t addr, const float4 fv[4]) {
    uint4 o0, o1;
    o0.x = pkh2(fv[0].x, fv[0].y); o0.y = pkh2(fv[0].z, fv[0].w);
    o0.z = pkh2(fv[1].x, fv[1].y); o0.w = pkh2(fv[1].z, fv[1].w);
    o1.x = pkh2(fv[2].x, fv[2].y); o1.y = pkh2(fv[2].z, fv[2].w);
    o1.z = pkh2(fv[3].x, fv[3].y); o1.w = pkh2(fv[3].z, fv[3].w);
    STSV4(addr, o0);
    STSV4(addr + 16, o1);
}

// ---------------- cvt: weights only ----------------
__global__ void cvt_w_kernel(const float* __restrict__ W1,
                             const float* __restrict__ W2) {
    const int WTOT = 4 * 32768;
    for (int j = blockIdx.x * blockDim.x + threadIdx.x; j < WTOT;
         j += gridDim.x * blockDim.x) {
        if (j < 3 * 32768) {
            int sec = j >> 15, m = j & 32767;
            int n = m >> 7, k = m & 127;
            float v = W1[(sec * 128 + k) * 256 + n];
            __half* dst = (sec == 0) ? g_W1sT : (sec == 1) ? g_W1rT : g_W1eT;
            dst[m] = __float2half_rn(v);
        } else {
            int m = j - 3 * 32768;
            int n = m >> 8, k = m & 255;
            g_W2T[m] = __float2half_rn(W2[k * 128 + n]);
        }
    }
}

// ---------------- merged precompute: P[n] = node[n] @ [W1s | W1r] ----------------
__global__ __launch_bounds__(512, 1)
void precompute_kernel(const float* __restrict__ node)
{
    extern __shared__ char smem[];
    const int tid = threadIdx.x;
    const int wid = tid >> 5, lane = tid & 31;
    const int lr = lane >> 2, lc = lane & 3;
    const int wm = wid >> 2, wn = wid & 3;
    const int n0 = blockIdx.x * 128;

    const int r = tid >> 2, q = tid & 3;
    int nr = n0 + r; if (nr >= N_NODES) nr = N_NODES - 1;
    const float* pA = node + (size_t)nr * 128 + q * 32;
    const int nw = tid >> 1, hw = tid & 1;

    const uint32_t sbX = smem_u32(smem + PF_X);
    const uint32_t sbW[2] = { smem_u32(smem + PF_W0), smem_u32(smem + PF_W1B) };
    const uint32_t dX = (uint32_t)(r * PXS + q * 32) * 2;
    const uint32_t dW = (uint32_t)(nw * WS + hw * 32) * 2;

    const int aoff_row = lane & 15;
    const int aoff_k   = (lane >> 4) << 3;
    const int boff_n   = ((lane >> 4) << 3) + (lane & 7);
    const int boff_k   = ((lane >> 3) & 1) << 3;

    // stage s = pass*2 + chunk; table = s>>1 (W1s, W1r), k-offset = (s&1)*64
    auto stageW = [&](int s) {
        const __half* tab = (s < 2) ? g_W1sT : g_W1rT;
        const __half* src = tab + (size_t)nw * 128 + hw * 32 + (s & 1) * 64;
        uint32_t dst = sbW[s & 1] + dW;
        #pragma unroll
        for (int k = 0; k < 4; k++) CP16(dst + 16 * k, src + 8 * k);
        CP_COMMIT();
    };

    // prologue: full X (K=128) + W s=0
    stageW(0);
    {
        float4 fv[4];
        #pragma unroll
        for (int s = 0; s < 4; s++) fv[s] = *(const float4*)(pA + 4 * s);
        cvt_store32B(sbX + dX, fv);
        #pragma unroll
        for (int s = 0; s < 4; s++) fv[s] = *(const float4*)(pA + 16 + 4 * s);
        cvt_store32B(sbX + dX + 32, fv);
    }
    CP_WAIT0();
    __syncthreads();

    float acc[2][8][4];
    #pragma unroll
    for (int i = 0; i < 2; i++)
        #pragma unroll
        for (int j = 0; j < 8; j++)
            #pragma unroll
            for (int qq = 0; qq < 4; qq++) acc[i][j][qq] = 0.f;

    for (int s = 0; s < 4; s++) {
        if (s < 3) stageW(s + 1);
        const int c = s & 1;
        const uint32_t wb = sbW[c];
        #pragma unroll
        for (int ks = 0; ks < 4; ks++) {
            uint32_t A[2][4];
            #pragma unroll
            for (int i = 0; i < 2; i++)
                ldsm4(A[i], sbX + (uint32_t)((wm * 32 + i * 16 + aoff_row) * PXS + c * 64 + ks * 16 + aoff_k) * 2);
            #pragma unroll
            for (int jp = 0; jp < 4; jp++) {
                uint32_t B[4];
                ldsm4(B, wb + (uint32_t)((wn * 64 + jp * 16 + boff_n) * WS + ks * 16 + boff_k) * 2);
                mma16(acc[0][2 * jp],     A[0], B[0], B[1]);
                mma16(acc[1][2 * jp],     A[1], B[0], B[1]);
                mma16(acc[0][2 * jp + 1], A[0], B[2], B[3]);
                mma16(acc[1][2 * jp + 1], A[1], B[2], B[3]);
            }
        }
        if (c == 1) {
            // end of pass p = s>>1: write P and reset acc
            const int cbase = (s >> 1) * 256;
            #pragma unroll
            for (int i = 0; i < 2; i++) {
                int row = n0 + wm * 32 + i * 16 + lr;
                #pragma unroll
                for (int j = 0; j < 8; j++) {
                    int col = wn * 64 + j * 8 + 2 * lc;
                    if (row < N_NODES)
                        *(uint32_t*)(g_P + (size_t)row * 512 + cbase + col) = pkh2(acc[i][j][0], acc[i][j][1]);
                    if (row + 8 < N_NODES)
                        *(uint32_t*)(g_P + (size_t)(row + 8) * 512 + cbase + col) = pkh2(acc[i][j][2], acc[i][j][3]);
                }
            }
            #pragma unroll
            for (int i = 0; i < 2; i++)
                #pragma unroll
                for (int j = 0; j < 8; j++)
                    #pragma unroll
                    for (int qq = 0; qq < 4; qq++) acc[i][j][qq] = 0.f;
        }
        if (s < 3) {
            CP_WAIT0();
            __syncthreads();
        }
    }
}

// ---------------- persistent main kernel: W2 resident (once), W1e streamed/tile ----------------
__global__ __launch_bounds__(NTH, 1)
void edge_mlp_h(const float* __restrict__ edge_attr,
                const int*   __restrict__ eidx,
                const float* __restrict__ b1,
                const float* __restrict__ b2,
                const float* __restrict__ gamma,
                const float* __restrict__ beta,
                float* __restrict__ out)
{
    extern __shared__ char smem[];
    float* smf = (float*)smem;
    const int tid = threadIdx.x;
    const int wid = tid >> 5, lane = tid & 31;
    const int lr = lane >> 2, lc = lane & 3;
    const int wm = wid >> 2, wn = wid & 3;

    if (tid < 256) smf[OF_B1 / 4 + tid] = b1[tid];
    if (tid < 128) {
        smf[OF_B2 / 4 + tid] = b2[tid];
        smf[OF_G  / 4 + tid] = gamma[tid];
        smf[OF_BT / 4 + tid] = beta[tid];
    }

    const int r = tid >> 2, q = tid & 3;
    const int nw = tid >> 1, hw = tid & 1;

    const uint32_t sbX[2] = { smem_u32(smem + OF_X0), smem_u32(smem + OF_X1) };
    const uint32_t sbW1[2] = { smem_u32(smem + OF_W10), smem_u32(smem + OF_W11) };
    const uint32_t sbHW = smem_u32(smem + OF_HW);
    const uint32_t sbW2 = smem_u32(smem + OF_W2R);
    const uint32_t dX  = (uint32_t)(r * XS + q * 16) * 2;
    const uint32_t dW1 = (uint32_t)(nw * WS + hw * 32) * 2;

    const int aoff_row = lane & 15;
    const int aoff_k   = (lane >> 4) << 3;
    const int boff_n   = ((lane >> 4) << 3) + (lane & 7);
    const int boff_k   = ((lane >> 3) & 1) << 3;

    // ---- one-time W2 resident preload (group committed; first tile's WAIT0 collects it) ----
    {
        const __half* s2 = g_W2T + (size_t)r * 256 + q * 64;
        uint32_t d2 = sbW2 + (uint32_t)(r * W2S + q * 64) * 2;
        #pragma unroll
        for (int s = 0; s < 8; s++) CP16(d2 + 16 * s, s2 + 8 * s);
        CP_COMMIT();
    }

    for (int t = blockIdx.x; t < NTILES; t += GRIDX) {
        const int e0 = t * TILE_M;
        if (tid < 128) {
            int e = e0 + tid;
            bool ok = e < E_TOT;
            ((int*)(smem + OF_SI))[tid] = ok ? eidx[e] : 0;
            ((int*)(smem + OF_RI))[tid] = ok ? eidx[E_TOT + e] : 0;
        }
        int eMine = e0 + r; if (eMine >= E_TOT) eMine = e0;
        const float* pE = edge_attr + (size_t)eMine * 128 + q * 16;

        // stage W1e chunk0 + X chunk0
        {
            const __half* s1 = g_W1eT + (size_t)nw * 128 + hw * 32;
            #pragma unroll
            for (int k = 0; k < 4; k++) CP16(sbW1[0] + dW1 + 16 * k, s1 + 8 * k);
            CP_COMMIT();
            float4 fv[4];
            #pragma unroll
            for (int s = 0; s < 4; s++) fv[s] = *(const float4*)(pE + 4 * s);
            cvt_store32B(sbX[0] + dX, fv);
        }
        CP_WAIT0();
        __syncthreads();

        // ======== GEMM1e: 2 chunks K=64; stage c1 under c0 ========
        float acc[2][8][4];
        #pragma unroll
        for (int i = 0; i < 2; i++)
            #pragma unroll
            for (int j = 0; j < 8; j++)
                #pragma unroll
                for (int qq = 0; qq < 4; qq++) acc[i][j][qq] = 0.f;

        for (int c = 0; c < 2; c++) {
            const bool pre = (c == 0);
            float4 fv[4];
            if (pre) {
                const __half* s1 = g_W1eT + (size_t)nw * 128 + hw * 32 + 64;
                #pragma unroll
                for (int k = 0; k < 4; k++) CP16(sbW1[1] + dW1 + 16 * k, s1 + 8 * k);
                CP_COMMIT();
                #pragma unroll
                for (int s = 0; s < 4; s++) fv[s] = *(const float4*)(pE + 64 + 4 * s);
            }
            const uint32_t xb = sbX[c];
            const uint32_t wb = sbW1[c];
            #pragma unroll
            for (int ks = 0; ks < 4; ks++) {
                uint32_t A[2][4];
                #pragma unroll
                for (int i = 0; i < 2; i++)
                    ldsm4(A[i], xb + (uint32_t)((wm * 32 + i * 16 + aoff_row) * XS + ks * 16 + aoff_k) * 2);
                #pragma unroll
                for (int jp = 0; jp < 4; jp++) {
                    uint32_t B[4];
                    ldsm4(B, wb + (uint32_t)((wn * 64 + jp * 16 + boff_n) * WS + ks * 16 + boff_k) * 2);
                    mma16(acc[0][2 * jp],     A[0], B[0], B[1]);
                    mma16(acc[1][2 * jp],     A[1], B[0], B[1]);
                    mma16(acc[0][2 * jp + 1], A[0], B[2], B[3]);
                    mma16(acc[1][2 * jp + 1], A[1], B[2], B[3]);
                }
            }
            if (pre) {
                cvt_store32B(sbX[1] + dX, fv);
                CP_WAIT0();
            }
            __syncthreads();
        }

        // ======== epilogue 1: H = fp16(relu(accE + Ps + Pr + b1)) -> HW region ========
        {
            __half* Hh = (__half*)(smem + OF_HW);
            const int* sI = (const int*)(smem + OF_SI);
            const int* rI = (const int*)(smem + OF_RI);
            #pragma unroll
            for (int i = 0; i < 2; i++) {
                int r0 = wm * 32 + i * 16 + lr;
                const __half* P0s = g_P + (size_t)sI[r0] * 512;
                const __half* P0r = g_P + (size_t)rI[r0] * 512 + 256;
                const __half* P1s = g_P + (size_t)sI[r0 + 8] * 512;
                const __half* P1r = g_P + (size_t)rI[r0 + 8] * 512 + 256;
                #pragma unroll
                for (int j = 0; j < 8; j++) {
                    int col = wn * 64 + j * 8 + 2 * lc;
                    float2 ps0 = __half22float2(*(const __half2*)(P0s + col));
                    float2 pr0 = __half22float2(*(const __half2*)(P0r + col));
                    float2 ps1 = __half22float2(*(const __half2*)(P1s + col));
                    float2 pr1 = __half22float2(*(const __half2*)(P1r + col));
                    float g0 = smf[OF_B1 / 4 + col], g1 = smf[OF_B1 / 4 + col + 1];
                    *(uint32_t*)(Hh + r0 * HS + col) =
                        pkh2(fmaxf(acc[i][j][0] + ps0.x + pr0.x + g0, 0.f),
                             fmaxf(acc[i][j][1] + ps0.y + pr0.y + g1, 0.f));
                    *(uint32_t*)(Hh + (r0 + 8) * HS + col) =
                        pkh2(fmaxf(acc[i][j][2] + ps1.x + pr1.x + g0, 0.f),
                             fmaxf(acc[i][j][3] + ps1.y + pr1.y + g1, 0.f));
                }
            }
        }
        __syncthreads();

        // ======== GEMM2: resident W2, zero staging ========
        float acc2[2][4][4];
        #pragma unroll
        for (int i = 0; i < 2; i++)
            #pragma unroll
            for (int j = 0; j < 4; j++)
                #pragma unroll
                for (int qq = 0; qq < 4; qq++) acc2[i][j][qq] = 0.f;

        for (int c = 0; c < 4; c++) {
            #pragma unroll
            for (int ks = 0; ks < 4; ks++) {
                uint32_t A[2][4];
                #pragma unroll
                for (int i = 0; i < 2; i++)
                    ldsm4(A[i], sbHW + (uint32_t)((wm * 32 + i * 16 + aoff_row) * HS + c * 64 + ks * 16 + aoff_k) * 2);
                #pragma unroll
                for (int jp = 0; jp < 2; jp++) {
                    uint32_t B[4];
                    ldsm4(B, sbW2 + (uint32_t)((wn * 32 + jp * 16 + boff_n) * W2S + c * 64 + ks * 16 + boff_k) * 2);
                    mma16(acc2[0][2 * jp],     A[0], B[0], B[1]);
                    mma16(acc2[1][2 * jp],     A[1], B[0], B[1]);
                    mma16(acc2[0][2 * jp + 1], A[0], B[2], B[3]);
                    mma16(acc2[1][2 * jp + 1], A[1], B[2], B[3]);
                }
            }
        }
        __syncthreads();   // H reads done; Of overwrites HW region

        // ======== epilogue 2: Of = C2 + b2 ; LayerNorm -> out ========
        {
            float* Of = (float*)(smem + OF_HW);
            #pragma unroll
            for (int i = 0; i < 2; i++) {
                int r0 = wm * 32 + i * 16 + lr;
                #pragma unroll
                for (int j = 0; j < 4; j++) {
                    int col = wn * 32 + j * 8 + 2 * lc;
                    float g0 = smf[OF_B2 / 4 + col], g1 = smf[OF_B2 / 4 + col + 1];
                    Of[r0 * OS + col]           = acc2[i][j][0] + g0;
                    Of[r0 * OS + col + 1]       = acc2[i][j][1] + g1;
                    Of[(r0 + 8) * OS + col]     = acc2[i][j][2] + g0;
                    Of[(r0 + 8) * OS + col + 1] = acc2[i][j][3] + g1;
                }
            }
        }
        __syncthreads();
        {
            const float* Of = (const float*)(smem + OF_HW);
            float4 ga = *(const float4*)(smf + OF_G  / 4 + 4 * lane);
            float4 bt = *(const float4*)(smf + OF_BT / 4 + 4 * lane);
            #pragma unroll
            for (int rr = 0; rr < 8; rr++) {
                int row = wid * 8 + rr;
                int e = e0 + row;
                float4 v = *(const float4*)(Of + row * OS + 4 * lane);
                float s = v.x + v.y + v.z + v.w;
                float qs = v.x * v.x + v.y * v.y + v.z * v.z + v.w * v.w;
                #pragma unroll
                for (int o = 16; o > 0; o >>= 1) {
                    s  += __shfl_xor_sync(0xffffffffu, s, o);
                    qs += __shfl_xor_sync(0xffffffffu, qs, o);
                }
                float mean = s * (1.0f / 128.0f);
                float var  = qs * (1.0f / 128.0f) - mean * mean;
                float inv  = rsqrtf(var + 1e-5f);
                if (e < E_TOT) {
                    float4 o4;
                    o4.x = (v.x - mean) * inv * ga.x + bt.x;
                    o4.y = (v.y - mean) * inv * ga.y + bt.y;
                    o4.z = (v.z - mean) * inv * ga.z + bt.z;
                    o4.w = (v.w - mean) * inv * ga.w + bt.w;
                    *(float4*)(out + (size_t)e * 128 + 4 * lane) = o4;
                }
            }
        }
        __syncthreads();   // Of reads done before next tile's W1e staging overwrites region
    }
}

extern "C" void kernel_launch(void* const* d_in, const int* in_sizes, int n_in,
                              void* d_out, int out_size)
{
    (void)in_sizes; (void)n_in; (void)out_size;
    cvt_w_kernel<<<512, 256>>>((const float*)d_in[3], (const float*)d_in[5]);
    cudaFuncSetAttribute(precompute_kernel,
                         cudaFuncAttributeMaxDynamicSharedMemorySize, SMEM_PRE);
    precompute_kernel<<<(N_NODES + 127) / 128, 512, SMEM_PRE>>>(
        (const float*)d_in[0]);
    cudaFuncSetAttribute(edge_mlp_h,
                         cudaFuncAttributeMaxDynamicSharedMemorySize, SMEM_BYTES);
    edge_mlp_h<<<GRIDX, NTH, SMEM_BYTES>>>(
        (const float*)d_in[1],   // edge_contact_attr
        (const int*)  d_in[2],   // edge_contact_index
        (const float*)d_in[4],   // b1
        (const float*)d_in[6],   // b2
        (const float*)d_in[7],   // ln_gamma
        (const float*)d_in[8],   // ln_beta
        (float*)d_out);
}